// round 5
// baseline (speedup 1.0000x reference)
#include <cuda_runtime.h>
#include <cuda_bf16.h>
#include <math.h>

// Problem constants
#define B_        4
#define S_        2048
#define IN_       1024
#define KVH       4
#define HD        64
#define ROWS_TOT  (B_ * S_)       // 8192
#define KVD       (KVH * HD)      // 256
#define PROJ_N    (3 * KVD)       // 768  (Qeff | K | V)

// ---------------- scratch (static __device__, no allocation) ----------------
__device__ float g_WqEff[IN_ * KVD];          // 1 MB
__device__ float g_Q[B_ * KVH * S_ * HD];     // 8 MB  layout [b][h][s][d]
__device__ float g_K[B_ * KVH * S_ * HD];     // 8 MB
__device__ float g_V[B_ * KVH * S_ * HD];     // 8 MB
__device__ float g_O[ROWS_TOT * KVD];         // 8 MB  layout [b][s][h][d]
__device__ float g_rope_cos[S_ * 32];         // 256 KB
__device__ float g_rope_sin[S_ * 32];         // 256 KB

// ---------------- kernel R: rope tables ----------------
__global__ void rope_table_kernel() {
    int idx = blockIdx.x * blockDim.x + threadIdx.x;
    if (idx >= S_ * 32) return;
    int srow = idx >> 5;
    int jj   = idx & 31;
    float theta = exp10f(-(float)jj);
    float ang   = (float)(srow + 1) * theta;
    float sn, cs;
    sincosf(ang, &sn, &cs);
    g_rope_cos[idx] = cs;
    g_rope_sin[idx] = sn;
}

// ---------------- kernel A: Wq_eff = sum over groups ----------------
__global__ void wqeff_kernel(const float* __restrict__ Wq) {
    int idx = blockIdx.x * blockDim.x + threadIdx.x;
    if (idx >= IN_ * KVD) return;
    int i   = idx >> 8;        // in_dim index
    int col = idx & 255;       // kv*64 + d
    int kv  = col >> 6;
    int d   = col & 63;
    const float* p = Wq + (size_t)i * 1024 + kv * 256 + d;
    g_WqEff[idx] = p[0] + p[64] + p[128] + p[192];
}

// ---------------- kernel B: fused projection GEMM + RoPE epilogue ----------------
#define BM 128
#define BN 64
#define BK 16

__global__ __launch_bounds__(256) void proj_kernel(
    const float* __restrict__ A,      // q: [8192 x 1024]
    const float* __restrict__ Wk,     // [1024 x 256]
    const float* __restrict__ Wv)     // [1024 x 256]
{
    __shared__ float As[BK][BM];   // 8 KB
    __shared__ float Bs[BK][BN];   // 4 KB

    int t = threadIdx.x;
    int rowBase  = blockIdx.y * BM;
    int colBase  = blockIdx.x * BN;          // 0..704
    int sec      = colBase >> 8;             // 0=Q, 1=K, 2=V (uniform per block)
    int lcolBase = colBase & 255;
    const float* Bsrc = (sec == 0) ? g_WqEff : (sec == 1 ? Wk : Wv);

    float acc[8][4];
#pragma unroll
    for (int i = 0; i < 8; i++)
#pragma unroll
        for (int j = 0; j < 4; j++) acc[i][j] = 0.f;

    int ty = t >> 4, tx = t & 15;

    for (int k0 = 0; k0 < IN_; k0 += BK) {
        // load A tile (128x16), transpose into As[k][m]
#pragma unroll
        for (int l = 0; l < 2; l++) {
            int f = t + l * 256;
            int ar = f >> 2, ac4 = f & 3;
            float4 v = *(const float4*)(A + (size_t)(rowBase + ar) * IN_ + k0 + ac4 * 4);
            As[ac4 * 4 + 0][ar] = v.x;
            As[ac4 * 4 + 1][ar] = v.y;
            As[ac4 * 4 + 2][ar] = v.z;
            As[ac4 * 4 + 3][ar] = v.w;
        }
        // load B tile (16x64)
        {
            int br = t >> 4, bc4 = t & 15;
            float4 v = *(const float4*)(Bsrc + (size_t)(k0 + br) * KVD + lcolBase + bc4 * 4);
            *(float4*)&Bs[br][bc4 * 4] = v;
        }
        __syncthreads();
#pragma unroll
        for (int k = 0; k < BK; k++) {
            float4 a0 = *(const float4*)&As[k][ty * 8];
            float4 a1 = *(const float4*)&As[k][ty * 8 + 4];
            float4 b0 = *(const float4*)&Bs[k][tx * 4];
            float a[8] = {a0.x, a0.y, a0.z, a0.w, a1.x, a1.y, a1.z, a1.w};
            float b[4] = {b0.x, b0.y, b0.z, b0.w};
#pragma unroll
            for (int i = 0; i < 8; i++)
#pragma unroll
                for (int j = 0; j < 4; j++) acc[i][j] += a[i] * b[j];
        }
        __syncthreads();
    }

    // Epilogue: write to [b][h][s][d]; apply RoPE for Q/K
    float* dst = (sec == 0) ? g_Q : (sec == 1 ? g_K : g_V);
#pragma unroll
    for (int i = 0; i < 8; i++) {
        int row  = rowBase + ty * 8 + i;
        int b    = row >> 11;
        int srow = row & 2047;
#pragma unroll
        for (int j = 0; j < 4; j += 2) {
            int lc = lcolBase + tx * 4 + j;     // even
            int h  = lc >> 6;
            int hd = lc & 63;
            float v0 = acc[i][j], v1 = acc[i][j + 1];
            size_t base = ((size_t)(b * KVH + h) * S_ + srow) * HD + hd;
            if (sec < 2) {
                int jj = hd >> 1;
                float cs = g_rope_cos[srow * 32 + jj];
                float sn = g_rope_sin[srow * 32 + jj];
                dst[base]     = v0 * cs - v1 * sn;
                dst[base + 1] = v0 * sn + v1 * cs;
            } else {
                dst[base]     = v0;
                dst[base + 1] = v1;
            }
        }
    }
}

// ---------------- kernel C: causal flash attention (fp32) ----------------
#define BR 64
#define BC 32

__global__ __launch_bounds__(256) void flash_kernel() {
    __shared__ float Qs[BR][HD];   // 16 KB
    __shared__ float Ks[BC][HD];   //  8 KB
    __shared__ float Vs[BC][HD];   //  8 KB
    __shared__ float Ps[BR][BC];   //  8 KB

    int t  = threadIdx.x;
    int r  = t >> 2;         // 0..63 : query row within tile
    int qt = t & 3;          // quarter
    int qb = blockIdx.x;     // 0..31
    int bh = blockIdx.y;     // 0..15 (= b*4 + h)

    const float* Qg = g_Q + (size_t)bh * S_ * HD + (size_t)qb * BR * HD;
    const float* Kg = g_K + (size_t)bh * S_ * HD;
    const float* Vg = g_V + (size_t)bh * S_ * HD;

    // load Q tile
#pragma unroll
    for (int l = 0; l < 4; l++) {
        int f = t + l * 256;
        int rr = f >> 4, c4 = f & 15;
        *(float4*)&Qs[rr][c4 * 4] = *(const float4*)(Qg + rr * HD + c4 * 4);
    }

    float m = -1e30f, lsum = 0.f;
    float o[16];
#pragma unroll
    for (int i = 0; i < 16; i++) o[i] = 0.f;

    int rowg = qb * BR + r;
    int nkb  = 2 * qb + 2;
    const float scale = 0.125f;   // 1/sqrt(64)

    for (int kb = 0; kb < nkb; kb++) {
        // load K,V tiles
#pragma unroll
        for (int l = 0; l < 2; l++) {
            int f = t + l * 256;
            int rr = f >> 4, c4 = f & 15;
            *(float4*)&Ks[rr][c4 * 4] = *(const float4*)(Kg + (size_t)(kb * BC + rr) * HD + c4 * 4);
            *(float4*)&Vs[rr][c4 * 4] = *(const float4*)(Vg + (size_t)(kb * BC + rr) * HD + c4 * 4);
        }
        __syncthreads();

        // scores: this thread owns cols [qt*8, qt*8+8) of the 32-wide KV tile
        float s[8];
#pragma unroll
        for (int c = 0; c < 8; c++) s[c] = 0.f;
#pragma unroll
        for (int d4 = 0; d4 < 16; d4++) {
            float4 q4 = *(const float4*)&Qs[r][d4 * 4];
#pragma unroll
            for (int c = 0; c < 8; c++) {
                float4 k4 = *(const float4*)&Ks[qt * 8 + c][d4 * 4];
                s[c] += q4.x * k4.x + q4.y * k4.y + q4.z * k4.z + q4.w * k4.w;
            }
        }

        float mx = -1e30f;
#pragma unroll
        for (int c = 0; c < 8; c++) {
            float v = s[c] * scale;
            int col = kb * BC + qt * 8 + c;
            if (col > rowg) v = -1e30f;
            s[c] = v;
            mx = fmaxf(mx, v);
        }
        // row max / row sum across the 4 lanes sharing this row
        mx = fmaxf(mx, __shfl_xor_sync(0xffffffffu, mx, 1));
        mx = fmaxf(mx, __shfl_xor_sync(0xffffffffu, mx, 2));
        float mnew  = fmaxf(m, mx);
        float alpha = expf(m - mnew);
        float ps = 0.f;
#pragma unroll
        for (int c = 0; c < 8; c++) {
            float p = expf(s[c] - mnew);
            Ps[r][qt * 8 + c] = p;
            ps += p;
        }
        ps += __shfl_xor_sync(0xffffffffu, ps, 1);
        ps += __shfl_xor_sync(0xffffffffu, ps, 2);
        lsum = lsum * alpha + ps;
        m = mnew;
#pragma unroll
        for (int i = 0; i < 16; i++) o[i] *= alpha;
        __syncwarp();   // Ps rows are produced/consumed within one warp

        // O update: this thread owns d-cols [qt*16, qt*16+16)
#pragma unroll
        for (int a = 0; a < BC; a++) {
            float p = Ps[r][a];
#pragma unroll
            for (int i4 = 0; i4 < 4; i4++) {
                float4 v4 = *(const float4*)&Vs[a][qt * 16 + i4 * 4];
                o[i4 * 4 + 0] += p * v4.x;
                o[i4 * 4 + 1] += p * v4.y;
                o[i4 * 4 + 2] += p * v4.z;
                o[i4 * 4 + 3] += p * v4.w;
            }
        }
        __syncthreads();
    }

    // normalize + write to [b][s][h][d]
    float inv = 1.f / lsum;
    int b = bh >> 2, h = bh & 3;
    int srow = qb * BR + r;
    float* Od = g_O + ((size_t)(b * S_ + srow) * KVH + h) * HD + qt * 16;
#pragma unroll
    for (int i4 = 0; i4 < 4; i4++) {
        float4 v;
        v.x = o[i4 * 4 + 0] * inv;
        v.y = o[i4 * 4 + 1] * inv;
        v.z = o[i4 * 4 + 2] * inv;
        v.w = o[i4 * 4 + 3] * inv;
        *(float4*)(Od + i4 * 4) = v;
    }
}

// ---------------- kernel D: output GEMM [8192x256]·[256x1024] ----------------
__global__ __launch_bounds__(256) void out_kernel(
    const float* __restrict__ Wo, float* __restrict__ Out)
{
    __shared__ float As[BK][BM];
    __shared__ float Bs[BK][BN];

    int t = threadIdx.x;
    int rowBase = blockIdx.y * BM;
    int colBase = blockIdx.x * BN;

    float acc[8][4];
#pragma unroll
    for (int i = 0; i < 8; i++)
#pragma unroll
        for (int j = 0; j < 4; j++) acc[i][j] = 0.f;

    int ty = t >> 4, tx = t & 15;

    for (int k0 = 0; k0 < KVD; k0 += BK) {
#pragma unroll
        for (int l = 0; l < 2; l++) {
            int f = t + l * 256;
            int ar = f >> 2, ac4 = f & 3;
            float4 v = *(const float4*)(g_O + (size_t)(rowBase + ar) * KVD + k0 + ac4 * 4);
            As[ac4 * 4 + 0][ar] = v.x;
            As[ac4 * 4 + 1][ar] = v.y;
            As[ac4 * 4 + 2][ar] = v.z;
            As[ac4 * 4 + 3][ar] = v.w;
        }
        {
            int br = t >> 4, bc4 = t & 15;
            float4 v = *(const float4*)(Wo + (size_t)(k0 + br) * IN_ + colBase + bc4 * 4);
            *(float4*)&Bs[br][bc4 * 4] = v;
        }
        __syncthreads();
#pragma unroll
        for (int k = 0; k < BK; k++) {
            float4 a0 = *(const float4*)&As[k][ty * 8];
            float4 a1 = *(const float4*)&As[k][ty * 8 + 4];
            float4 b0 = *(const float4*)&Bs[k][tx * 4];
            float a[8] = {a0.x, a0.y, a0.z, a0.w, a1.x, a1.y, a1.z, a1.w};
            float b[4] = {b0.x, b0.y, b0.z, b0.w};
#pragma unroll
            for (int i = 0; i < 8; i++)
#pragma unroll
                for (int j = 0; j < 4; j++) acc[i][j] += a[i] * b[j];
        }
        __syncthreads();
    }

#pragma unroll
    for (int i = 0; i < 8; i++) {
        int row = rowBase + ty * 8 + i;
        float4 v;
        v.x = acc[i][0]; v.y = acc[i][1]; v.z = acc[i][2]; v.w = acc[i][3];
        *(float4*)(Out + (size_t)row * IN_ + colBase + tx * 4) = v;
    }
}

// ---------------- launch ----------------
extern "C" void kernel_launch(void* const* d_in, const int* in_sizes, int n_in,
                              void* d_out, int out_size) {
    const float* q  = (const float*)d_in[0];
    // d_in[1] = mask (tril ones) — causal, handled analytically
    const float* Wq = (const float*)d_in[2];
    const float* Wk = (const float*)d_in[3];
    const float* Wv = (const float*)d_in[4];
    const float* Wo = (const float*)d_in[5];
    float* out = (float*)d_out;

    rope_table_kernel<<<(S_ * 32 + 255) / 256, 256>>>();
    wqeff_kernel<<<(IN_ * KVD + 255) / 256, 256>>>(Wq);

    dim3 gp(PROJ_N / BN, ROWS_TOT / BM);   // (12, 64)
    proj_kernel<<<gp, 256>>>(q, Wk, Wv);

    dim3 gf(S_ / BR, B_ * KVH);            // (32, 16)
    flash_kernel<<<gf, 256>>>();

    dim3 go(IN_ / BN, ROWS_TOT / BM);      // (16, 64)
    out_kernel<<<go, 256>>>(Wo, out);
}

// round 6
// speedup vs baseline: 8.7863x; 8.7863x over previous
#include <cuda_runtime.h>
#include <cuda_bf16.h>
#include <math.h>

// Problem constants
#define B_        4
#define S_        2048
#define IN_       1024
#define KVH       4
#define HD        64
#define ROWS_TOT  (B_ * S_)       // 8192
#define KVD       (KVH * HD)      // 256
#define PROJ_N    (3 * KVD)       // 768  (Qeff | K | V)

#define L2E 1.4426950408889634f

// ---------------- scratch (static __device__, no allocation) ----------------
__device__ float g_WqEff[IN_ * KVD];          // 1 MB
__device__ float g_Q[B_ * KVH * S_ * HD];     // 8 MB  layout [b][h][s][d]
__device__ float g_K[B_ * KVH * S_ * HD];     // 8 MB
__device__ float g_V[B_ * KVH * S_ * HD];     // 8 MB
__device__ float g_O[ROWS_TOT * KVD];         // 8 MB  layout [b][s][h][d]
__device__ float g_rope_cos[S_ * 32];
__device__ float g_rope_sin[S_ * 32];

// ---------------- tf32 helpers ----------------
__device__ __forceinline__ unsigned f2tf(float x) {
    unsigned r; asm("cvt.rna.tf32.f32 %0, %1;" : "=r"(r) : "f"(x)); return r;
}
__device__ __forceinline__ float f2tff(float x) {
    return __uint_as_float(f2tf(x));
}
__device__ __forceinline__ void mma_tf32(float* c, const unsigned* a, const unsigned* b) {
    asm volatile(
        "mma.sync.aligned.m16n8k8.row.col.f32.tf32.tf32.f32 "
        "{%0,%1,%2,%3}, {%4,%5,%6,%7}, {%8,%9}, {%0,%1,%2,%3};"
        : "+f"(c[0]), "+f"(c[1]), "+f"(c[2]), "+f"(c[3])
        : "r"(a[0]), "r"(a[1]), "r"(a[2]), "r"(a[3]), "r"(b[0]), "r"(b[1]));
}

// ---------------- kernel R: rope tables ----------------
__global__ void rope_table_kernel() {
    int idx = blockIdx.x * blockDim.x + threadIdx.x;
    if (idx >= S_ * 32) return;
    int srow = idx >> 5;
    int jj   = idx & 31;
    float theta = exp10f(-(float)jj);
    float ang   = (float)(srow + 1) * theta;
    float sn, cs;
    sincosf(ang, &sn, &cs);
    g_rope_cos[idx] = cs;
    g_rope_sin[idx] = sn;
}

// ---------------- kernel A: Wq_eff = sum over groups ----------------
__global__ void wqeff_kernel(const float* __restrict__ Wq) {
    int idx = blockIdx.x * blockDim.x + threadIdx.x;
    if (idx >= IN_ * KVD) return;
    int i   = idx >> 8;
    int col = idx & 255;
    int kv  = col >> 6;
    int d   = col & 63;
    const float* p = Wq + (size_t)i * 1024 + kv * 256 + d;
    g_WqEff[idx] = p[0] + p[64] + p[128] + p[192];
}

// ---------------- kernel B: tf32-mma projection GEMM + RoPE epilogue ----------------
// Block: 128(M) x 64(N), BK=32. 8 warps; warp tile 32x32 (2 Mtiles x 4 Ntiles).
#define PBM 128
#define PBN 64
#define PBK 32

__global__ __launch_bounds__(256) void proj_mma_kernel(
    const float* __restrict__ A,      // q: [8192 x 1024]
    const float* __restrict__ Wk,     // [1024 x 256]
    const float* __restrict__ Wv)
{
    __shared__ float As[PBM][PBK + 4];   // m-major: frag banks 4g+c (free)
    __shared__ float Bs[PBK][PBN + 8];   // k-major: frag banks 8c+g (free)

    int t = threadIdx.x, lane = t & 31, w = t >> 5;
    int g = lane >> 2, c = lane & 3;
    int rowBase  = blockIdx.y * PBM;
    int colBase  = blockIdx.x * PBN;
    int sec      = colBase >> 8;
    int lcolBase = colBase & 255;
    const float* Bsrc = (sec == 0) ? g_WqEff : (sec == 1 ? Wk : Wv);

    int wm = (w >> 1) * 32, wn = (w & 1) * 32;
    float acc[2][4][4];
#pragma unroll
    for (int mt = 0; mt < 2; mt++)
#pragma unroll
        for (int nt = 0; nt < 4; nt++)
#pragma unroll
            for (int i = 0; i < 4; i++) acc[mt][nt][i] = 0.f;

    for (int k0 = 0; k0 < IN_; k0 += PBK) {
        // A tile: 128x32 floats, float4 along k (coalesced), 4 per thread
#pragma unroll
        for (int l = 0; l < 4; l++) {
            int f = t + l * 256;
            int ar = f >> 3, ac4 = f & 7;
            float4 v = *(const float4*)(A + (size_t)(rowBase + ar) * IN_ + k0 + ac4 * 4);
            v.x = f2tff(v.x); v.y = f2tff(v.y); v.z = f2tff(v.z); v.w = f2tff(v.w);
            *(float4*)&As[ar][ac4 * 4] = v;
        }
        // B tile: 32x64 floats, 2 float4 per thread
#pragma unroll
        for (int l = 0; l < 2; l++) {
            int f = t + l * 256;
            int br = f >> 4, bc4 = f & 15;
            float4 v = *(const float4*)(Bsrc + (size_t)(k0 + br) * KVD + lcolBase + bc4 * 4);
            v.x = f2tff(v.x); v.y = f2tff(v.y); v.z = f2tff(v.z); v.w = f2tff(v.w);
            *(float4*)&Bs[br][bc4 * 4] = v;
        }
        __syncthreads();

#pragma unroll
        for (int ks = 0; ks < 4; ks++) {
            unsigned af[2][4], bf[4][2];
#pragma unroll
            for (int mt = 0; mt < 2; mt++) {
                int m = wm + mt * 16 + g;
                af[mt][0] = __float_as_uint(As[m][ks * 8 + c]);
                af[mt][1] = __float_as_uint(As[m + 8][ks * 8 + c]);
                af[mt][2] = __float_as_uint(As[m][ks * 8 + c + 4]);
                af[mt][3] = __float_as_uint(As[m + 8][ks * 8 + c + 4]);
            }
#pragma unroll
            for (int nt = 0; nt < 4; nt++) {
                int n = wn + nt * 8 + g;
                bf[nt][0] = __float_as_uint(Bs[ks * 8 + c][n]);
                bf[nt][1] = __float_as_uint(Bs[ks * 8 + c + 4][n]);
            }
#pragma unroll
            for (int mt = 0; mt < 2; mt++)
#pragma unroll
                for (int nt = 0; nt < 4; nt++)
                    mma_tf32(acc[mt][nt], af[mt], bf[nt]);
        }
        __syncthreads();
    }

    // Epilogue: RoPE for sections Q/K, plain store for V. Cols 2c,2c+1 are even/odd pair.
    float* dst = (sec == 0) ? g_Q : (sec == 1 ? g_K : g_V);
#pragma unroll
    for (int mt = 0; mt < 2; mt++)
#pragma unroll
        for (int h = 0; h < 2; h++) {
            int row  = rowBase + wm + mt * 16 + g + 8 * h;
            int b    = row >> 11;
            int srow = row & 2047;
#pragma unroll
            for (int nt = 0; nt < 4; nt++) {
                int lc = lcolBase + wn + nt * 8 + 2 * c;   // even
                int hh = lc >> 6, hd = lc & 63;
                float v0 = acc[mt][nt][2 * h], v1 = acc[mt][nt][2 * h + 1];
                size_t base = ((size_t)(b * KVH + hh) * S_ + srow) * HD + hd;
                float2 o;
                if (sec < 2) {
                    int jj = hd >> 1;
                    float cs = g_rope_cos[srow * 32 + jj];
                    float sn = g_rope_sin[srow * 32 + jj];
                    o.x = v0 * cs - v1 * sn;
                    o.y = v0 * sn + v1 * cs;
                } else {
                    o.x = v0; o.y = v1;
                }
                *(float2*)(dst + base) = o;
            }
        }
}

// ---------------- kernel C: tf32-mma causal flash attention ----------------
// Block: BR=128 Q rows, BC=32 KV cols per iteration. 8 warps x 16 rows each.
// Q fragments register-resident for the whole kernel (pre-scaled by 1/8).
#define FBR 128
#define FBC 32

__global__ __launch_bounds__(256) void flash_mma_kernel() {
    __shared__ float Ks[FBC][HD + 4];    // frag pattern row=g: banks 4g+c (free)
    __shared__ float Vs[FBC][HD + 8];    // frag pattern row=c: banks 8c+g (free)
    __shared__ float Ps[FBR][FBC + 4];   // A-frag pattern row=g: banks 4g+c (free)

    int t = threadIdx.x, lane = t & 31, w = t >> 5;
    int g = lane >> 2, c = lane & 3;
    int bid = blockIdx.x;
    int qb = 15 - (bid >> 4);    // heavy blocks first
    int bh = bid & 15;

    const float* Qg = g_Q + (size_t)bh * S_ * HD + (size_t)qb * FBR * HD;
    const float* Kg = g_K + (size_t)bh * S_ * HD;
    const float* Vg = g_V + (size_t)bh * S_ * HD;

    // Q fragments: 8 k-slices x 4 regs, scaled by 0.125 (exact) then tf32-rounded
    unsigned qf[8][4];
    int r0 = w * 16 + g;
#pragma unroll
    for (int ks = 0; ks < 8; ks++) {
        qf[ks][0] = f2tf(Qg[(size_t)r0 * HD + ks * 8 + c] * 0.125f);
        qf[ks][1] = f2tf(Qg[(size_t)(r0 + 8) * HD + ks * 8 + c] * 0.125f);
        qf[ks][2] = f2tf(Qg[(size_t)r0 * HD + ks * 8 + c + 4] * 0.125f);
        qf[ks][3] = f2tf(Qg[(size_t)(r0 + 8) * HD + ks * 8 + c + 4] * 0.125f);
    }

    float oacc[8][4];
#pragma unroll
    for (int i = 0; i < 8; i++)
#pragma unroll
        for (int j = 0; j < 4; j++) oacc[i][j] = 0.f;

    float m0 = -1e30f, m1 = -1e30f, l0 = 0.f, l1 = 0.f;
    int rowg0 = qb * FBR + w * 16 + g;   // global query row (half 0); half1 = +8
    int nkb = 4 * qb + 4;

    for (int kb = 0; kb < nkb; kb++) {
        // cooperative K/V tile load (32x64 each), tf32-rounded
#pragma unroll
        for (int l = 0; l < 2; l++) {
            int f = t + l * 256;
            int rr = f >> 4, c4 = f & 15;
            float4 kv = *(const float4*)(Kg + (size_t)(kb * FBC + rr) * HD + c4 * 4);
            kv.x = f2tff(kv.x); kv.y = f2tff(kv.y); kv.z = f2tff(kv.z); kv.w = f2tff(kv.w);
            *(float4*)&Ks[rr][c4 * 4] = kv;
            float4 vv = *(const float4*)(Vg + (size_t)(kb * FBC + rr) * HD + c4 * 4);
            vv.x = f2tff(vv.x); vv.y = f2tff(vv.y); vv.z = f2tff(vv.z); vv.w = f2tff(vv.w);
            *(float4*)&Vs[rr][c4 * 4] = vv;
        }
        __syncthreads();

        // S = Q * K^T  (pre-scaled logits land directly)
        float sacc[4][4];
#pragma unroll
        for (int nt = 0; nt < 4; nt++)
#pragma unroll
            for (int i = 0; i < 4; i++) sacc[nt][i] = 0.f;
#pragma unroll
        for (int ks = 0; ks < 8; ks++) {
            unsigned bf[4][2];
#pragma unroll
            for (int nt = 0; nt < 4; nt++) {
                bf[nt][0] = __float_as_uint(Ks[nt * 8 + g][ks * 8 + c]);
                bf[nt][1] = __float_as_uint(Ks[nt * 8 + g][ks * 8 + c + 4]);
            }
#pragma unroll
            for (int nt = 0; nt < 4; nt++)
                mma_tf32(sacc[nt], qf[ks], bf[nt]);
        }

        // causal mask + row max (two row-halves per thread)
        int colb = kb * FBC + 2 * c;
        float mx0 = -1e30f, mx1 = -1e30f;
#pragma unroll
        for (int nt = 0; nt < 4; nt++) {
#pragma unroll
            for (int j = 0; j < 2; j++) {
                int col = colb + nt * 8 + j;
                if (col > rowg0)     sacc[nt][j]     = -1e30f;
                if (col > rowg0 + 8) sacc[nt][2 + j] = -1e30f;
                mx0 = fmaxf(mx0, sacc[nt][j]);
                mx1 = fmaxf(mx1, sacc[nt][2 + j]);
            }
        }
        mx0 = fmaxf(mx0, __shfl_xor_sync(0xffffffffu, mx0, 1));
        mx0 = fmaxf(mx0, __shfl_xor_sync(0xffffffffu, mx0, 2));
        mx1 = fmaxf(mx1, __shfl_xor_sync(0xffffffffu, mx1, 1));
        mx1 = fmaxf(mx1, __shfl_xor_sync(0xffffffffu, mx1, 2));

        float mn0 = fmaxf(m0, mx0), mn1 = fmaxf(m1, mx1);
        float al0 = exp2f((m0 - mn0) * L2E), al1 = exp2f((m1 - mn1) * L2E);

        float ps0 = 0.f, ps1 = 0.f;
        int pr0 = w * 16 + g;
#pragma unroll
        for (int nt = 0; nt < 4; nt++) {
            float p0 = f2tff(exp2f((sacc[nt][0] - mn0) * L2E));
            float p1 = f2tff(exp2f((sacc[nt][1] - mn0) * L2E));
            float p2 = f2tff(exp2f((sacc[nt][2] - mn1) * L2E));
            float p3 = f2tff(exp2f((sacc[nt][3] - mn1) * L2E));
            *(float2*)&Ps[pr0][nt * 8 + 2 * c]     = make_float2(p0, p1);
            *(float2*)&Ps[pr0 + 8][nt * 8 + 2 * c] = make_float2(p2, p3);
            ps0 += p0 + p1;
            ps1 += p2 + p3;
        }
        ps0 += __shfl_xor_sync(0xffffffffu, ps0, 1);
        ps0 += __shfl_xor_sync(0xffffffffu, ps0, 2);
        ps1 += __shfl_xor_sync(0xffffffffu, ps1, 1);
        ps1 += __shfl_xor_sync(0xffffffffu, ps1, 2);

        l0 = l0 * al0 + ps0;
        l1 = l1 * al1 + ps1;
        m0 = mn0; m1 = mn1;

#pragma unroll
        for (int nt2 = 0; nt2 < 8; nt2++) {
            oacc[nt2][0] *= al0; oacc[nt2][1] *= al0;
            oacc[nt2][2] *= al1; oacc[nt2][3] *= al1;
        }
        __syncwarp();   // Ps slice is warp-private

        // O += P * V
#pragma unroll
        for (int ks2 = 0; ks2 < 4; ks2++) {
            unsigned pa[4];
            pa[0] = __float_as_uint(Ps[pr0][ks2 * 8 + c]);
            pa[1] = __float_as_uint(Ps[pr0 + 8][ks2 * 8 + c]);
            pa[2] = __float_as_uint(Ps[pr0][ks2 * 8 + c + 4]);
            pa[3] = __float_as_uint(Ps[pr0 + 8][ks2 * 8 + c + 4]);
#pragma unroll
            for (int nt2 = 0; nt2 < 8; nt2++) {
                unsigned vb[2];
                vb[0] = __float_as_uint(Vs[ks2 * 8 + c][nt2 * 8 + g]);
                vb[1] = __float_as_uint(Vs[ks2 * 8 + c + 4][nt2 * 8 + g]);
                mma_tf32(oacc[nt2], pa, vb);
            }
        }
        __syncthreads();
    }

    // normalize + write [b][s][h][d]
    float inv0 = 1.f / l0, inv1 = 1.f / l1;
    int b = bh >> 2, h = bh & 3;
    int srow = qb * FBR + w * 16 + g;
    float* O0 = g_O + ((size_t)(b * S_ + srow) * KVH + h) * HD;
    float* O1 = g_O + ((size_t)(b * S_ + srow + 8) * KVH + h) * HD;
#pragma unroll
    for (int nt2 = 0; nt2 < 8; nt2++) {
        *(float2*)(O0 + nt2 * 8 + 2 * c) = make_float2(oacc[nt2][0] * inv0, oacc[nt2][1] * inv0);
        *(float2*)(O1 + nt2 * 8 + 2 * c) = make_float2(oacc[nt2][2] * inv1, oacc[nt2][3] * inv1);
    }
}

// ---------------- kernel D: tf32-mma output GEMM [8192x256]*[256x1024] ----------------
__global__ __launch_bounds__(256) void out_mma_kernel(
    const float* __restrict__ Wo, float* __restrict__ Out)
{
    __shared__ float As[PBM][PBK + 4];
    __shared__ float Bs[PBK][PBN + 8];

    int t = threadIdx.x, lane = t & 31, w = t >> 5;
    int g = lane >> 2, c = lane & 3;
    int rowBase = blockIdx.y * PBM;
    int colBase = blockIdx.x * PBN;

    int wm = (w >> 1) * 32, wn = (w & 1) * 32;
    float acc[2][4][4];
#pragma unroll
    for (int mt = 0; mt < 2; mt++)
#pragma unroll
        for (int nt = 0; nt < 4; nt++)
#pragma unroll
            for (int i = 0; i < 4; i++) acc[mt][nt][i] = 0.f;

    for (int k0 = 0; k0 < KVD; k0 += PBK) {
#pragma unroll
        for (int l = 0; l < 4; l++) {
            int f = t + l * 256;
            int ar = f >> 3, ac4 = f & 7;
            float4 v = *(const float4*)(g_O + (size_t)(rowBase + ar) * KVD + k0 + ac4 * 4);
            v.x = f2tff(v.x); v.y = f2tff(v.y); v.z = f2tff(v.z); v.w = f2tff(v.w);
            *(float4*)&As[ar][ac4 * 4] = v;
        }
#pragma unroll
        for (int l = 0; l < 2; l++) {
            int f = t + l * 256;
            int br = f >> 4, bc4 = f & 15;
            float4 v = *(const float4*)(Wo + (size_t)(k0 + br) * IN_ + colBase + bc4 * 4);
            v.x = f2tff(v.x); v.y = f2tff(v.y); v.z = f2tff(v.z); v.w = f2tff(v.w);
            *(float4*)&Bs[br][bc4 * 4] = v;
        }
        __syncthreads();

#pragma unroll
        for (int ks = 0; ks < 4; ks++) {
            unsigned af[2][4], bf[4][2];
#pragma unroll
            for (int mt = 0; mt < 2; mt++) {
                int m = wm + mt * 16 + g;
                af[mt][0] = __float_as_uint(As[m][ks * 8 + c]);
                af[mt][1] = __float_as_uint(As[m + 8][ks * 8 + c]);
                af[mt][2] = __float_as_uint(As[m][ks * 8 + c + 4]);
                af[mt][3] = __float_as_uint(As[m + 8][ks * 8 + c + 4]);
            }
#pragma unroll
            for (int nt = 0; nt < 4; nt++) {
                int n = wn + nt * 8 + g;
                bf[nt][0] = __float_as_uint(Bs[ks * 8 + c][n]);
                bf[nt][1] = __float_as_uint(Bs[ks * 8 + c + 4][n]);
            }
#pragma unroll
            for (int mt = 0; mt < 2; mt++)
#pragma unroll
                for (int nt = 0; nt < 4; nt++)
                    mma_tf32(acc[mt][nt], af[mt], bf[nt]);
        }
        __syncthreads();
    }

#pragma unroll
    for (int mt = 0; mt < 2; mt++)
#pragma unroll
        for (int h = 0; h < 2; h++) {
            int row = rowBase + wm + mt * 16 + g + 8 * h;
#pragma unroll
            for (int nt = 0; nt < 4; nt++) {
                int col = colBase + wn + nt * 8 + 2 * c;
                *(float2*)(Out + (size_t)row * IN_ + col) =
                    make_float2(acc[mt][nt][2 * h], acc[mt][nt][2 * h + 1]);
            }
        }
}

// ---------------- launch ----------------
extern "C" void kernel_launch(void* const* d_in, const int* in_sizes, int n_in,
                              void* d_out, int out_size) {
    const float* q  = (const float*)d_in[0];
    // d_in[1] = mask (tril ones) — handled analytically as causal
    const float* Wq = (const float*)d_in[2];
    const float* Wk = (const float*)d_in[3];
    const float* Wv = (const float*)d_in[4];
    const float* Wo = (const float*)d_in[5];
    float* out = (float*)d_out;

    rope_table_kernel<<<(S_ * 32 + 255) / 256, 256>>>();
    wqeff_kernel<<<(IN_ * KVD + 255) / 256, 256>>>(Wq);

    dim3 gp(PROJ_N / PBN, ROWS_TOT / PBM);   // (12, 64)
    proj_mma_kernel<<<gp, 256>>>(q, Wk, Wv);

    flash_mma_kernel<<<(S_ / FBR) * (B_ * KVH), 256>>>();   // 256 blocks, heavy-first

    dim3 go(IN_ / PBN, ROWS_TOT / PBM);      // (16, 64)
    out_mma_kernel<<<go, 256>>>(Wo, out);
}